// round 3
// baseline (speedup 1.0000x reference)
#include <cuda_runtime.h>
#include <cuda_bf16.h>
#include <cstdint>

// ============================================================================
// Problem constants
// ============================================================================
static constexpr int BROWS = 16384;   // B*L rows of H
static constexpr int DK    = 1024;    // K (hidden dim)
static constexpr int NPAD  = 1024;    // padded N: dep 0..499 | 0 | head 512..1011 | 0
static constexpr int MLP   = 500;

static constexpr int BM = 128, BN = 128, BK = 32;
static constexpr int NIT = DK / BK;   // 32

// Scratch (device globals; no allocation allowed)
__device__ __align__(16) __nv_bfloat16 g_Bhi[NPAD * DK];
__device__ __align__(16) __nv_bfloat16 g_Blo[NPAD * DK];
__device__ __align__(16) float g_scores[BROWS * 4];   // [row][dep0,dep1,head0,head1]
__device__ __align__(16) float g_wc0[NPAD];
__device__ __align__(16) float g_wc1[NPAD];
__device__ __align__(16) float g_bias[NPAD];

// ============================================================================
// Small helpers
// ============================================================================
__device__ __forceinline__ uint32_t smem_u32(const void* p) {
    uint32_t a;
    asm("{ .reg .u64 t; cvta.to.shared.u64 t, %1; cvt.u32.u64 %0, t; }" : "=r"(a) : "l"(p));
    return a;
}
__device__ __forceinline__ void ldsm_x4(uint32_t* r, uint32_t addr) {
    asm volatile("ldmatrix.sync.aligned.m8n8.x4.shared.b16 {%0,%1,%2,%3}, [%4];"
                 : "=r"(r[0]), "=r"(r[1]), "=r"(r[2]), "=r"(r[3]) : "r"(addr));
}
__device__ __forceinline__ void mma_16816(float* c, const uint32_t* a, const uint32_t* b) {
    asm volatile(
        "mma.sync.aligned.m16n8k16.row.col.f32.bf16.bf16.f32 "
        "{%0,%1,%2,%3}, {%4,%5,%6,%7}, {%8,%9}, {%0,%1,%2,%3};"
        : "+f"(c[0]), "+f"(c[1]), "+f"(c[2]), "+f"(c[3])
        : "r"(a[0]), "r"(a[1]), "r"(a[2]), "r"(a[3]), "r"(b[0]), "r"(b[1]));
}
__device__ __forceinline__ uint32_t pack_bf16x2(__nv_bfloat16 lo, __nv_bfloat16 hi) {
    return ((uint32_t)__bfloat16_as_ushort(hi) << 16) | __bfloat16_as_ushort(lo);
}

// ============================================================================
// Prep: transpose+pad+split weights to bf16 hi/lo, fuse wc/bias vectors, zero scores
// ============================================================================
__global__ __launch_bounds__(256) void prep_kernel(
    const float* __restrict__ Wd, const float* __restrict__ Wh,
    const float* __restrict__ bd, const float* __restrict__ bh,
    const float* __restrict__ Wc)
{
    int idx = blockIdx.x * 256 + threadIdx.x;   // 0 .. 1024*1024-1
    int k = idx >> 10;
    int n = idx & 1023;
    float w = 0.f;
    if (n < MLP)                       w = Wd[k * MLP + n];
    else if (n >= 512 && n < 512+MLP)  w = Wh[k * MLP + (n - 512)];
    __nv_bfloat16 h = __float2bfloat16(w);
    g_Bhi[n * DK + k] = h;
    g_Blo[n * DK + k] = __float2bfloat16(w - __bfloat162float(h));

    if (k == 0) {
        float c0 = 0.f, c1 = 0.f, bb = 0.f;
        if (n < MLP)                      { c0 = Wc[n*2]; c1 = Wc[n*2+1]; bb = bd[n]; }
        else if (n >= 512 && n < 512+MLP) { int m = n - 512 + MLP;
                                            c0 = Wc[m*2]; c1 = Wc[m*2+1]; bb = bh[n-512]; }
        g_wc0[n] = c0; g_wc1[n] = c1; g_bias[n] = bb;
    }
    if (idx < BROWS * 4) g_scores[idx] = 0.f;
}

// ============================================================================
// GEMM: mma.sync bf16 split (Ah*Bh + Ah*Bl + Al*Bh), fused bias+lrelu+wc epilogue
// ============================================================================
// Smem tiles: padded row stride 40 bf16 (80 B) -> conflict-free ldmatrix
static constexpr int SSTR = 40;                       // bf16 elems per smem row
static constexpr int STILE = 128 * SSTR;              // elems per tile

__global__ __launch_bounds__(256, 1) void gemm_kernel(const float* __restrict__ H)
{
    __shared__ __align__(16) __nv_bfloat16 sAhi[STILE];
    __shared__ __align__(16) __nv_bfloat16 sAlo[STILE];
    __shared__ __align__(16) __nv_bfloat16 sBhi[STILE];
    __shared__ __align__(16) __nv_bfloat16 sBlo[STILE];

    const int tid  = threadIdx.x;
    const int l    = tid & 31;
    const int wid  = tid >> 5;
    const int wm   = wid & 1;          // warp m index (0..1), tile m64
    const int wn   = wid >> 1;         // warp n index (0..3), tile n32
    const int nbase = blockIdx.x * BN;
    const int rbase = blockIdx.y * BM;

    const uint32_t sAhiB = smem_u32(sAhi);
    const uint32_t sAloB = smem_u32(sAlo);
    const uint32_t sBhiB = smem_u32(sBhi);
    const uint32_t sBloB = smem_u32(sBlo);

    // ldmatrix lane address offsets (bytes) within a tile
    // A tiles: m16 x k16 at (wm*64 + mt*16, s*16)
    const uint32_t aLane = (uint32_t)((wm * 64 + (l & 15)) * 80 + (l >> 4) * 16);
    // B tiles: n16 x k16 at (wn*32 + j*16, s*16)
    const uint32_t bLane = (uint32_t)((wn * 32 + (l & 7) + ((l >> 4) << 3)) * 80 + ((l & 8) ? 16 : 0));

    // ---- Global load indexing ----
    // A: 128x32 f32 = 1024 float4 chunks; thread handles chunks tid + i*256
    // B: 128x32 bf16 = 512 16B chunks per array; thread handles chunks tid, tid+256
    const float4* Hv  = reinterpret_cast<const float4*>(H);
    const uint4*  Bhv = reinterpret_cast<const uint4*>(g_Bhi);
    const uint4*  Blv = reinterpret_cast<const uint4*>(g_Blo);

    uint32_t aHiReg[4][2], aLoReg[4][2];   // per i: 4 f32 -> 2 b32 hi, 2 b32 lo
    uint4    bHiReg[2], bLoReg[2];

    // A chunk geometry (constant across kt)
    int aRow[4], aC4[4];
    #pragma unroll
    for (int i = 0; i < 4; ++i) {
        int ch = tid + i * 256;
        aRow[i] = ch >> 3;        // 8 float4 per 32-f32 row
        aC4[i]  = ch & 7;
    }
    int bRow[2], bC[2];
    #pragma unroll
    for (int i = 0; i < 2; ++i) {
        int ch = tid + i * 256;
        bRow[i] = ch >> 2;        // 4 x16B per 32-bf16 row
        bC[i]   = ch & 3;
    }

    auto load_regs = [&](int kt) {
        #pragma unroll
        for (int i = 0; i < 4; ++i) {
            const float4 v = __ldg(Hv + (size_t)(rbase + aRow[i]) * 256 + kt * 8 + aC4[i]);
            const __nv_bfloat16 h0 = __float2bfloat16(v.x);
            const __nv_bfloat16 h1 = __float2bfloat16(v.y);
            const __nv_bfloat16 h2 = __float2bfloat16(v.z);
            const __nv_bfloat16 h3 = __float2bfloat16(v.w);
            aHiReg[i][0] = pack_bf16x2(h0, h1);
            aHiReg[i][1] = pack_bf16x2(h2, h3);
            aLoReg[i][0] = pack_bf16x2(__float2bfloat16(v.x - __bfloat162float(h0)),
                                       __float2bfloat16(v.y - __bfloat162float(h1)));
            aLoReg[i][1] = pack_bf16x2(__float2bfloat16(v.z - __bfloat162float(h2)),
                                       __float2bfloat16(v.w - __bfloat162float(h3)));
        }
        #pragma unroll
        for (int i = 0; i < 2; ++i) {
            const size_t gi = (size_t)(nbase + bRow[i]) * 128 + kt * 4 + bC[i];
            bHiReg[i] = __ldg(Bhv + gi);
            bLoReg[i] = __ldg(Blv + gi);
        }
    };
    auto store_smem = [&]() {
        #pragma unroll
        for (int i = 0; i < 4; ++i) {
            uint32_t off = (uint32_t)(aRow[i] * SSTR + aC4[i] * 4);   // elems
            *reinterpret_cast<uint2*>(sAhi + off) = make_uint2(aHiReg[i][0], aHiReg[i][1]);
            *reinterpret_cast<uint2*>(sAlo + off) = make_uint2(aLoReg[i][0], aLoReg[i][1]);
        }
        #pragma unroll
        for (int i = 0; i < 2; ++i) {
            uint32_t off = (uint32_t)(bRow[i] * SSTR + bC[i] * 8);
            *reinterpret_cast<uint4*>(sBhi + off) = bHiReg[i];
            *reinterpret_cast<uint4*>(sBlo + off) = bLoReg[i];
        }
    };

    float acc[4][4][4];   // [mt][n8][c-frag 4]
    #pragma unroll
    for (int a = 0; a < 4; ++a)
        #pragma unroll
        for (int b = 0; b < 4; ++b)
            #pragma unroll
            for (int c = 0; c < 4; ++c) acc[a][b][c] = 0.f;

    load_regs(0);
    for (int kt = 0; kt < NIT; ++kt) {
        __syncthreads();                 // previous mma done reading smem
        store_smem();
        __syncthreads();
        if (kt + 1 < NIT) load_regs(kt + 1);   // LDG in flight under the MMAs

        #pragma unroll
        for (int pass = 0; pass < 3; ++pass) {
            const uint32_t aB = (pass == 2) ? sAloB : sAhiB;
            const uint32_t bB = (pass == 1) ? sBloB : sBhiB;
            #pragma unroll
            for (int s = 0; s < 2; ++s) {
                uint32_t afr[4][4], bfr[2][4];
                #pragma unroll
                for (int mt = 0; mt < 4; ++mt)
                    ldsm_x4(afr[mt], aB + aLane + (uint32_t)(mt * 16 * 80) + (uint32_t)(s * 32));
                #pragma unroll
                for (int j = 0; j < 2; ++j)
                    ldsm_x4(bfr[j], bB + bLane + (uint32_t)(j * 16 * 80) + (uint32_t)(s * 32));
                #pragma unroll
                for (int mt = 0; mt < 4; ++mt) {
                    #pragma unroll
                    for (int j = 0; j < 2; ++j) {
                        mma_16816(acc[mt][2*j+0], afr[mt], &bfr[j][0]);
                        mma_16816(acc[mt][2*j+1], afr[mt], &bfr[j][2]);
                    }
                }
            }
        }
    }

    // ---- Epilogue: bias + LeakyReLU + dot wc, 4-lane reduce, atomic into scores ----
    const int quad = l >> 2, qlane = l & 3;
    const int slot = (blockIdx.x >= 4) ? 2 : 0;
    #pragma unroll
    for (int mt = 0; mt < 4; ++mt) {
        float s00 = 0.f, s01 = 0.f, s10 = 0.f, s11 = 0.f;  // [rowhalf][out]
        #pragma unroll
        for (int n8 = 0; n8 < 4; ++n8) {
            const int n = nbase + wn * 32 + n8 * 8 + qlane * 2;
            const float b0 = __ldg(g_bias + n),  b1 = __ldg(g_bias + n + 1);
            const float u0 = __ldg(g_wc0 + n),   u1 = __ldg(g_wc0 + n + 1);
            const float v0 = __ldg(g_wc1 + n),   v1 = __ldg(g_wc1 + n + 1);
            float y;
            y = acc[mt][n8][0] + b0; y = (y > 0.f) ? y : 0.01f * y; s00 = fmaf(y, u0, s00); s01 = fmaf(y, v0, s01);
            y = acc[mt][n8][1] + b1; y = (y > 0.f) ? y : 0.01f * y; s00 = fmaf(y, u1, s00); s01 = fmaf(y, v1, s01);
            y = acc[mt][n8][2] + b0; y = (y > 0.f) ? y : 0.01f * y; s10 = fmaf(y, u0, s10); s11 = fmaf(y, v0, s11);
            y = acc[mt][n8][3] + b1; y = (y > 0.f) ? y : 0.01f * y; s10 = fmaf(y, u1, s10); s11 = fmaf(y, v1, s11);
        }
        s00 += __shfl_xor_sync(0xFFFFFFFF, s00, 1); s00 += __shfl_xor_sync(0xFFFFFFFF, s00, 2);
        s01 += __shfl_xor_sync(0xFFFFFFFF, s01, 1); s01 += __shfl_xor_sync(0xFFFFFFFF, s01, 2);
        s10 += __shfl_xor_sync(0xFFFFFFFF, s10, 1); s10 += __shfl_xor_sync(0xFFFFFFFF, s10, 2);
        s11 += __shfl_xor_sync(0xFFFFFFFF, s11, 1); s11 += __shfl_xor_sync(0xFFFFFFFF, s11, 2);
        if (qlane == 0) {
            const int rowA = rbase + wm * 64 + mt * 16 + quad;
            atomicAdd(&g_scores[rowA * 4 + slot],           s00);
            atomicAdd(&g_scores[rowA * 4 + slot + 1],       s01);
            atomicAdd(&g_scores[(rowA + 8) * 4 + slot],     s10);
            atomicAdd(&g_scores[(rowA + 8) * 4 + slot + 1], s11);
        }
    }
}

// ============================================================================
// Broadcast: out[b,i,j,c] = dep[b,i,c] + head[b,j,c] + bc[c]  (128 MiB stream)
// ============================================================================
__global__ __launch_bounds__(256) void bcast_kernel(const float* __restrict__ bc,
                                                    float4* __restrict__ out)
{
    const int bi = blockIdx.x;              // b*1024 + i
    const int b  = bi >> 10;
    const float d0 = g_scores[bi * 4 + 0] + __ldg(bc + 0);
    const float d1 = g_scores[bi * 4 + 1] + __ldg(bc + 1);
    const float2* hs = reinterpret_cast<const float2*>(g_scores + ((size_t)b << 12));
    float4* o = out + (size_t)bi * 512;
    const int t = threadIdx.x;
    const int j = t * 4;
    const float2 h0 = __ldg(hs + (j + 0) * 2 + 1);
    const float2 h1 = __ldg(hs + (j + 1) * 2 + 1);
    const float2 h2 = __ldg(hs + (j + 2) * 2 + 1);
    const float2 h3 = __ldg(hs + (j + 3) * 2 + 1);
    o[t * 2 + 0] = make_float4(d0 + h0.x, d1 + h0.y, d0 + h1.x, d1 + h1.y);
    o[t * 2 + 1] = make_float4(d0 + h2.x, d1 + h2.y, d0 + h3.x, d1 + h3.y);
}

// ============================================================================
// Launch
// ============================================================================
extern "C" void kernel_launch(void* const* d_in, const int* in_sizes, int n_in,
                              void* d_out, int out_size)
{
    const float* H  = (const float*)d_in[0];
    const float* Wd = (const float*)d_in[1];
    const float* bd = (const float*)d_in[2];
    const float* Wh = (const float*)d_in[3];
    const float* bh = (const float*)d_in[4];
    const float* Wc = (const float*)d_in[5];
    const float* bc = (const float*)d_in[6];
    float* out = (float*)d_out;

    prep_kernel<<<(NPAD * DK) / 256, 256>>>(Wd, Wh, bd, bh, Wc);
    gemm_kernel<<<dim3(NPAD / BN, BROWS / BM), 256>>>(H);
    bcast_kernel<<<BROWS, 256>>>(bc, (float4*)out);
}

// round 4
// speedup vs baseline: 1.5149x; 1.5149x over previous
#include <cuda_runtime.h>
#include <cuda_bf16.h>
#include <cstdint>

// ============================================================================
// Problem constants
// ============================================================================
static constexpr int BROWS = 16384;   // B*L rows of H
static constexpr int DK    = 1024;    // K (hidden dim)
static constexpr int NPAD  = 1024;    // padded N: dep 0..499 | 0 | head 512..1011 | 0
static constexpr int MLP   = 500;

static constexpr int BM = 128, BN = 128, BK = 32;
static constexpr int NIT = DK / BK;   // 32
static constexpr int STAGES = 4;

// Scratch (device globals; no allocation allowed)
__device__ __align__(16) __nv_bfloat16 g_Ahi[BROWS * DK];   // 32 MB
__device__ __align__(16) __nv_bfloat16 g_Alo[BROWS * DK];   // 32 MB
__device__ __align__(16) __nv_bfloat16 g_Bhi[NPAD * DK];
__device__ __align__(16) __nv_bfloat16 g_Blo[NPAD * DK];
__device__ __align__(16) float g_scores[BROWS * 4];   // [row][dep0,dep1,head0,head1]
__device__ __align__(16) float g_wc0[NPAD];
__device__ __align__(16) float g_wc1[NPAD];
__device__ __align__(16) float g_bias[NPAD];

// ============================================================================
// Helpers
// ============================================================================
__device__ __forceinline__ uint32_t smem_u32(const void* p) {
    uint32_t a;
    asm("{ .reg .u64 t; cvta.to.shared.u64 t, %1; cvt.u32.u64 %0, t; }" : "=r"(a) : "l"(p));
    return a;
}
__device__ __forceinline__ void ldsm_x4(uint32_t* r, uint32_t addr) {
    asm volatile("ldmatrix.sync.aligned.m8n8.x4.shared.b16 {%0,%1,%2,%3}, [%4];"
                 : "=r"(r[0]), "=r"(r[1]), "=r"(r[2]), "=r"(r[3]) : "r"(addr));
}
__device__ __forceinline__ void mma_16816(float* c, const uint32_t* a, const uint32_t* b) {
    asm volatile(
        "mma.sync.aligned.m16n8k16.row.col.f32.bf16.bf16.f32 "
        "{%0,%1,%2,%3}, {%4,%5,%6,%7}, {%8,%9}, {%0,%1,%2,%3};"
        : "+f"(c[0]), "+f"(c[1]), "+f"(c[2]), "+f"(c[3])
        : "r"(a[0]), "r"(a[1]), "r"(a[2]), "r"(a[3]), "r"(b[0]), "r"(b[1]));
}
__device__ __forceinline__ uint32_t pack_bf16x2(__nv_bfloat16 lo, __nv_bfloat16 hi) {
    return ((uint32_t)__bfloat16_as_ushort(hi) << 16) | __bfloat16_as_ushort(lo);
}
#define CP16(dst, src) \
    asm volatile("cp.async.cg.shared.global [%0], [%1], 16;" :: "r"(dst), "l"(src) : "memory")
#define CP_COMMIT() asm volatile("cp.async.commit_group;" ::: "memory")
#define CP_WAIT(n)  asm volatile("cp.async.wait_group %0;" :: "n"(n) : "memory")

// XOR-swizzled byte offset for 16B chunk c (0..3) in row r (64B rows)
__device__ __forceinline__ uint32_t swz(int r, int c) {
    return (uint32_t)(r * 64 + ((c ^ ((r >> 1) & 3)) << 4));
}

// ============================================================================
// Prep: transpose+pad+split weights to bf16 hi/lo, fuse wc/bias, zero scores
// One block per output row n (coalesced uint2 writes).
// ============================================================================
__global__ __launch_bounds__(256) void prep_kernel(
    const float* __restrict__ Wd, const float* __restrict__ Wh,
    const float* __restrict__ bd, const float* __restrict__ bh,
    const float* __restrict__ Wc)
{
    const int n  = blockIdx.x;
    const int k0 = threadIdx.x * 4;
    __nv_bfloat16 hi[4], lo[4];
    #pragma unroll
    for (int i = 0; i < 4; ++i) {
        float w = 0.f;
        if (n < MLP)                        w = __ldg(Wd + (k0 + i) * MLP + n);
        else if (n >= 512 && n < 512 + MLP) w = __ldg(Wh + (k0 + i) * MLP + (n - 512));
        hi[i] = __float2bfloat16(w);
        lo[i] = __float2bfloat16(w - __bfloat162float(hi[i]));
    }
    uint2 vh = make_uint2(pack_bf16x2(hi[0], hi[1]), pack_bf16x2(hi[2], hi[3]));
    uint2 vl = make_uint2(pack_bf16x2(lo[0], lo[1]), pack_bf16x2(lo[2], lo[3]));
    *reinterpret_cast<uint2*>(g_Bhi + n * DK + k0) = vh;
    *reinterpret_cast<uint2*>(g_Blo + n * DK + k0) = vl;

    if (threadIdx.x == 0) {
        float c0 = 0.f, c1 = 0.f, bb = 0.f;
        if (n < MLP)                      { c0 = Wc[n*2]; c1 = Wc[n*2+1]; bb = bd[n]; }
        else if (n >= 512 && n < 512+MLP) { int m = n - 512 + MLP;
                                            c0 = Wc[m*2]; c1 = Wc[m*2+1]; bb = bh[n-512]; }
        g_wc0[n] = c0; g_wc1[n] = c1; g_bias[n] = bb;
    }
    if (blockIdx.x < 256) g_scores[blockIdx.x * 256 + threadIdx.x] = 0.f;
}

// ============================================================================
// A-split: H f32 -> Ahi/Alo bf16 (coalesced stream)
// ============================================================================
__global__ __launch_bounds__(256) void asplit_kernel(const float4* __restrict__ Hv)
{
    const int idx = blockIdx.x * 256 + threadIdx.x;   // float4 index
    const float4 v = __ldg(Hv + idx);
    const __nv_bfloat16 h0 = __float2bfloat16(v.x);
    const __nv_bfloat16 h1 = __float2bfloat16(v.y);
    const __nv_bfloat16 h2 = __float2bfloat16(v.z);
    const __nv_bfloat16 h3 = __float2bfloat16(v.w);
    uint2 hv = make_uint2(pack_bf16x2(h0, h1), pack_bf16x2(h2, h3));
    uint2 lv = make_uint2(
        pack_bf16x2(__float2bfloat16(v.x - __bfloat162float(h0)),
                    __float2bfloat16(v.y - __bfloat162float(h1))),
        pack_bf16x2(__float2bfloat16(v.z - __bfloat162float(h2)),
                    __float2bfloat16(v.w - __bfloat162float(h3))));
    reinterpret_cast<uint2*>(g_Ahi)[idx] = hv;
    reinterpret_cast<uint2*>(g_Alo)[idx] = lv;
}

// ============================================================================
// GEMM: 4-stage cp.async pipeline, bf16 split (Ah*Bh + Ah*Bl + Al*Bh),
// fused bias+lrelu+wc epilogue
// ============================================================================
static constexpr int TILE_B   = 8192;            // 128 rows x 64 B
static constexpr int SUB_AHI = 0, SUB_ALO = 8192, SUB_BHI = 16384, SUB_BLO = 24576;
static constexpr int STAGE_B  = 4 * TILE_B;      // 32 KB
static constexpr int SMEM_BYTES = STAGES * STAGE_B;   // 128 KB

__global__ __launch_bounds__(256, 1) void gemm_kernel()
{
    extern __shared__ char smem[];
    const uint32_t sb = smem_u32(smem);

    const int tid = threadIdx.x;
    const int l   = tid & 31;
    const int wid = tid >> 5;
    const int wm  = wid & 1;           // warp m (0..1) -> m64
    const int wn  = wid >> 1;          // warp n (0..3) -> n32
    const int nbase = blockIdx.x * BN;
    const int rbase = blockIdx.y * BM;

    // ---- cp.async per-thread geometry: 2 chunks per tile ----
    int cpR[2], cpC[2];
    uint32_t cpS[2];
    size_t gA[2], gB[2];
    #pragma unroll
    for (int i = 0; i < 2; ++i) {
        cpR[i] = (tid >> 2) + i * 64;
        cpC[i] = tid & 3;
        cpS[i] = swz(cpR[i], cpC[i]);
        gA[i]  = (size_t)(rbase + cpR[i]) * 2048 + cpC[i] * 16;  // bytes
        gB[i]  = (size_t)(nbase + cpR[i]) * 2048 + cpC[i] * 16;
    }
    const char* pAhi = reinterpret_cast<const char*>(g_Ahi);
    const char* pAlo = reinterpret_cast<const char*>(g_Alo);
    const char* pBhi = reinterpret_cast<const char*>(g_Bhi);
    const char* pBlo = reinterpret_cast<const char*>(g_Blo);

    auto issue = [&](int slice) {
        const uint32_t stg = sb + (slice % STAGES) * STAGE_B;
        const size_t ko = (size_t)slice * 64;   // byte offset along K
        #pragma unroll
        for (int i = 0; i < 2; ++i) {
            CP16(stg + SUB_AHI + cpS[i], pAhi + gA[i] + ko);
            CP16(stg + SUB_ALO + cpS[i], pAlo + gA[i] + ko);
            CP16(stg + SUB_BHI + cpS[i], pBhi + gB[i] + ko);
            CP16(stg + SUB_BLO + cpS[i], pBlo + gB[i] + ko);
        }
        CP_COMMIT();
    };

    // ---- ldmatrix per-thread geometry ----
    uint32_t aOff[4], aXor[4];
    #pragma unroll
    for (int mt = 0; mt < 4; ++mt) {
        const int r = wm * 64 + mt * 16 + (l & 15);
        aOff[mt] = (uint32_t)(r * 64);
        aXor[mt] = (uint32_t)((r >> 1) & 3);
    }
    const int cA = l >> 4;              // 0/1
    uint32_t bOff[2], bXor[2];
    #pragma unroll
    for (int j = 0; j < 2; ++j) {
        const int r = wn * 32 + j * 16 + (l & 7) + ((l >> 4) << 3);
        bOff[j] = (uint32_t)(r * 64);
        bXor[j] = (uint32_t)((r >> 1) & 3);
    }
    const int cB = (l & 8) ? 1 : 0;

    float acc[4][4][4];
    #pragma unroll
    for (int a = 0; a < 4; ++a)
        #pragma unroll
        for (int b = 0; b < 4; ++b)
            #pragma unroll
            for (int c = 0; c < 4; ++c) acc[a][b][c] = 0.f;

    // ---- Prologue: fill STAGES-1 stages ----
    #pragma unroll
    for (int s = 0; s < STAGES - 1; ++s) issue(s);

    for (int kt = 0; kt < NIT; ++kt) {
        if (kt + STAGES - 1 < NIT) issue(kt + STAGES - 1);
        else CP_COMMIT();                       // keep group counting uniform
        CP_WAIT(STAGES - 1);
        __syncthreads();

        const uint32_t stg = sb + (kt % STAGES) * STAGE_B;
        #pragma unroll
        for (int s = 0; s < 2; ++s) {
            uint32_t ah[4][4], al[4][4], bh[2][4], bl[2][4];
            const int ca = s * 2 + cA;
            const int cb = s * 2 + cB;
            #pragma unroll
            for (int mt = 0; mt < 4; ++mt) {
                const uint32_t off = aOff[mt] + (((uint32_t)ca ^ aXor[mt]) << 4);
                ldsm_x4(ah[mt], stg + SUB_AHI + off);
                ldsm_x4(al[mt], stg + SUB_ALO + off);
            }
            #pragma unroll
            for (int j = 0; j < 2; ++j) {
                const uint32_t off = bOff[j] + (((uint32_t)cb ^ bXor[j]) << 4);
                ldsm_x4(bh[j], stg + SUB_BHI + off);
                ldsm_x4(bl[j], stg + SUB_BLO + off);
            }
            #pragma unroll
            for (int mt = 0; mt < 4; ++mt) {
                #pragma unroll
                for (int j = 0; j < 2; ++j) {
                    mma_16816(acc[mt][2*j+0], ah[mt], &bh[j][0]);
                    mma_16816(acc[mt][2*j+1], ah[mt], &bh[j][2]);
                    mma_16816(acc[mt][2*j+0], ah[mt], &bl[j][0]);
                    mma_16816(acc[mt][2*j+1], ah[mt], &bl[j][2]);
                    mma_16816(acc[mt][2*j+0], al[mt], &bh[j][0]);
                    mma_16816(acc[mt][2*j+1], al[mt], &bh[j][2]);
                }
            }
        }
        __syncthreads();
    }

    // ---- Epilogue: bias + LeakyReLU + dot wc, 4-lane reduce, atomic into scores ----
    const int quad = l >> 2, qlane = l & 3;
    const int slot = (blockIdx.x >= 4) ? 2 : 0;
    #pragma unroll
    for (int mt = 0; mt < 4; ++mt) {
        float s00 = 0.f, s01 = 0.f, s10 = 0.f, s11 = 0.f;
        #pragma unroll
        for (int n8 = 0; n8 < 4; ++n8) {
            const int n = nbase + wn * 32 + n8 * 8 + qlane * 2;
            const float b0 = __ldg(g_bias + n),  b1 = __ldg(g_bias + n + 1);
            const float u0 = __ldg(g_wc0 + n),   u1 = __ldg(g_wc0 + n + 1);
            const float v0 = __ldg(g_wc1 + n),   v1 = __ldg(g_wc1 + n + 1);
            float y;
            y = acc[mt][n8][0] + b0; y = (y > 0.f) ? y : 0.01f * y; s00 = fmaf(y, u0, s00); s01 = fmaf(y, v0, s01);
            y = acc[mt][n8][1] + b1; y = (y > 0.f) ? y : 0.01f * y; s00 = fmaf(y, u1, s00); s01 = fmaf(y, v1, s01);
            y = acc[mt][n8][2] + b0; y = (y > 0.f) ? y : 0.01f * y; s10 = fmaf(y, u0, s10); s11 = fmaf(y, v0, s11);
            y = acc[mt][n8][3] + b1; y = (y > 0.f) ? y : 0.01f * y; s10 = fmaf(y, u1, s10); s11 = fmaf(y, v1, s11);
        }
        s00 += __shfl_xor_sync(0xFFFFFFFF, s00, 1); s00 += __shfl_xor_sync(0xFFFFFFFF, s00, 2);
        s01 += __shfl_xor_sync(0xFFFFFFFF, s01, 1); s01 += __shfl_xor_sync(0xFFFFFFFF, s01, 2);
        s10 += __shfl_xor_sync(0xFFFFFFFF, s10, 1); s10 += __shfl_xor_sync(0xFFFFFFFF, s10, 2);
        s11 += __shfl_xor_sync(0xFFFFFFFF, s11, 1); s11 += __shfl_xor_sync(0xFFFFFFFF, s11, 2);
        if (qlane == 0) {
            const int rowA = rbase + wm * 64 + mt * 16 + quad;
            atomicAdd(&g_scores[rowA * 4 + slot],           s00);
            atomicAdd(&g_scores[rowA * 4 + slot + 1],       s01);
            atomicAdd(&g_scores[(rowA + 8) * 4 + slot],     s10);
            atomicAdd(&g_scores[(rowA + 8) * 4 + slot + 1], s11);
        }
    }
}

// ============================================================================
// Broadcast: out[b,i,j,c] = dep[b,i,c] + head[b,j,c] + bc[c]  (128 MiB stream)
// ============================================================================
__global__ __launch_bounds__(256) void bcast_kernel(const float* __restrict__ bc,
                                                    float4* __restrict__ out)
{
    const int bi = blockIdx.x;              // b*1024 + i
    const int b  = bi >> 10;
    const float d0 = g_scores[bi * 4 + 0] + __ldg(bc + 0);
    const float d1 = g_scores[bi * 4 + 1] + __ldg(bc + 1);
    const float2* hs = reinterpret_cast<const float2*>(g_scores + ((size_t)b << 12));
    float4* o = out + (size_t)bi * 512;
    const int t = threadIdx.x;
    const int j = t * 4;
    const float2 h0 = __ldg(hs + (j + 0) * 2 + 1);
    const float2 h1 = __ldg(hs + (j + 1) * 2 + 1);
    const float2 h2 = __ldg(hs + (j + 2) * 2 + 1);
    const float2 h3 = __ldg(hs + (j + 3) * 2 + 1);
    o[t * 2 + 0] = make_float4(d0 + h0.x, d1 + h0.y, d0 + h1.x, d1 + h1.y);
    o[t * 2 + 1] = make_float4(d0 + h2.x, d1 + h2.y, d0 + h3.x, d1 + h3.y);
}

// ============================================================================
// Launch
// ============================================================================
extern "C" void kernel_launch(void* const* d_in, const int* in_sizes, int n_in,
                              void* d_out, int out_size)
{
    const float* H  = (const float*)d_in[0];
    const float* Wd = (const float*)d_in[1];
    const float* bd = (const float*)d_in[2];
    const float* Wh = (const float*)d_in[3];
    const float* bh = (const float*)d_in[4];
    const float* Wc = (const float*)d_in[5];
    const float* bc = (const float*)d_in[6];
    float* out = (float*)d_out;

    prep_kernel<<<NPAD, 256>>>(Wd, Wh, bd, bh, Wc);
    asplit_kernel<<<(BROWS * DK / 4) / 256, 256>>>((const float4*)H);

    static bool attr_set = false;
    if (!attr_set) {
        cudaFuncSetAttribute(gemm_kernel, cudaFuncAttributeMaxDynamicSharedMemorySize, SMEM_BYTES);
        attr_set = true;
    }
    gemm_kernel<<<dim3(NPAD / BN, BROWS / BM), 256, SMEM_BYTES>>>();

    bcast_kernel<<<BROWS, 256>>>(bc, (float4*)out);
}